// round 10
// baseline (speedup 1.0000x reference)
#include <cuda_runtime.h>
#include <cuda_fp16.h>

#define SB 2
#define SX 160
#define SY 192
#define SZ 160
#define WIN 21
#define HALF 10
#define NF 9830400ull          // SB*SX*SY*SZ
#define YP (SY / 2)            // 96 y-pairs
#define YSEG 3
#define YL (SY / YSEG)         // 64
#define XSEG 8
#define XLEN (SX / XSEG)       // 20
#define NPART (SB * YP * XSEG) // 1536
#define LPAD (SZ + 2 * HALF)   // 180
#define S1N (SZ + 18)          // stage1 physical range
#define RDEP 11                // ring depth in y-PAIRS (covers 22 lines)
#define NBLK_AB (SB * SX * YSEG)

// 4 channels packed as half2 (lane = y parity): x=(I), y=(J), z=(I2), w=(J2)
struct __align__(16) HQ { __half2 x, y, z, w; };

__device__ HQ g_q2[NF / 2];            // y-pair-packed output of passAB
__device__ __half2 g_e2[NF / 2];       // IJ channel
__device__ HQ g_rq[(size_t)NBLK_AB * RDEP * SZ];      // gmem ring (L2-resident)
__device__ __half2 g_re[(size_t)NBLK_AB * RDEP * SZ];
__device__ double g_part[NPART];
__device__ int g_count;

// ---------------------------------------------------------------------------
// Fused pass A+B, y-pair packed. z-filter = 3-tap then 7-tap-stride-3 packed
// HADD2 stages (both y-lines at once). y-filter = per-thread running sums in
// native half; subtrahends from a GMEM pair-ring prefetched at iteration
// start (L2 latency hidden behind two barriers + tap work). Next pair's
// input lines prefetched one iteration ahead. YSEG=3 -> 960 blocks fills
// one full resident wave (~6.5 blocks/SM).
// ---------------------------------------------------------------------------
__global__ __launch_bounds__(SZ) void passAB(const float* __restrict__ I,
                                             const float* __restrict__ J) {
    __shared__ HQ      lQ[LPAD];
    __shared__ __half2 lE[LPAD];
    __shared__ HQ      s1Q[S1N];
    __shared__ __half2 s1E[S1N];

    const int z = threadIdx.x;
    int bid = blockIdx.x;
    const int seg = bid % YSEG;
    int t = bid / YSEG;
    const int x = t % SX;
    const int b = t / SX;

    const __half2 zero2 = __floats2half2_rn(0.f, 0.f);
    const __half zeroh = __float2half(0.f);

    if (z < HALF) {
        HQ z4; z4.x = zero2; z4.y = zero2; z4.z = zero2; z4.w = zero2;
        lQ[z] = z4; lQ[SZ + HALF + z] = z4;
        lE[z] = zero2; lE[SZ + HALF + z] = zero2;
    }

    const int y0 = seg * YL;
    const int y1 = y0 + YL;
    const int ystart = (y0 - HALF > 0) ? (y0 - HALF) : 0;  // even (54, 118)
    const size_t planeBase = ((size_t)(b * SX + x)) * SY * SZ;
    const size_t ringBase = (size_t)bid * RDEP;

    __half c0 = zeroh, c1 = zeroh, c2 = zeroh, c3 = zeroh, c4 = zeroh;

    // preload the first pair's input lines
    float pi0 = 0.f, pj0 = 0.f, pi1 = 0.f, pj1 = 0.f;
    {
        size_t o = planeBase + (size_t)ystart * SZ + z;
        pi0 = I[o]; pj0 = J[o];
        if (ystart + 1 < SY) {
            size_t o1 = o + SZ;
            pi1 = I[o1]; pj1 = J[o1];
        }
    }

    __syncthreads();

    int it = 0;
    for (int y = ystart; y < y1 + HALF; y += 2, ++it) {
        // ---- ring prefetch (consumed after phase 2) ----
        const int slot = it % RDEP;
        const int slotn = (slot + 1 == RDEP) ? 0 : slot + 1;
        const size_t ro = (ringBase + slot) * SZ + z;
        const size_t rn = (ringBase + slotn) * SZ + z;
        HQ hd, hn; __half2 hed, hen;
        hd.x = zero2; hd.y = zero2; hd.z = zero2; hd.w = zero2; hed = zero2;
        hn = hd; hen = zero2;
        if (it >= 11) { hd = g_rq[ro]; hed = g_re[ro]; }   // lane1 of pair it-11
        if (it >= 10) { hn = g_rq[rn]; hen = g_re[rn]; }   // lane0 of pair it-10

        // ---- phase 0: products of the preloaded pair, stage to smem ----
        {
            HQ h;
            h.x = __floats2half2_rn(pi0, pi1);
            h.y = __floats2half2_rn(pj0, pj1);
            h.z = __hmul2(h.x, h.x);
            h.w = __hmul2(h.y, h.y);
            lQ[HALF + z] = h;
            lE[HALF + z] = __hmul2(h.x, h.y);
        }

        // ---- prefetch next pair's input lines ----
        pi0 = 0.f; pj0 = 0.f; pi1 = 0.f; pj1 = 0.f;
        {
            const int yn = y + 2;
            if (yn < y1 + HALF) {
                if (yn < SY) {
                    size_t o = planeBase + (size_t)yn * SZ + z;
                    pi0 = I[o]; pj0 = J[o];
                }
                if (yn + 1 < SY) {
                    size_t o = planeBase + (size_t)(yn + 1) * SZ + z;
                    pi1 = I[o]; pj1 = J[o];
                }
            }
        }
        __syncthreads();

        // ---- phase 1: 3-tap stage (both lines at once) ----
        {
            const int i = z;
            HQ a0 = lQ[i], a1 = lQ[i + 1], a2 = lQ[i + 2];
            HQ r;
            r.x = __hadd2(__hadd2(a0.x, a1.x), a2.x);
            r.y = __hadd2(__hadd2(a0.y, a1.y), a2.y);
            r.z = __hadd2(__hadd2(a0.z, a1.z), a2.z);
            r.w = __hadd2(__hadd2(a0.w, a1.w), a2.w);
            s1Q[i] = r;
            s1E[i] = __hadd2(__hadd2(lE[i], lE[i + 1]), lE[i + 2]);
        }
        if (z < S1N - SZ) {
            const int i = SZ + z;
            HQ a0 = lQ[i], a1 = lQ[i + 1], a2 = lQ[i + 2];
            HQ r;
            r.x = __hadd2(__hadd2(a0.x, a1.x), a2.x);
            r.y = __hadd2(__hadd2(a0.y, a1.y), a2.y);
            r.z = __hadd2(__hadd2(a0.z, a1.z), a2.z);
            r.w = __hadd2(__hadd2(a0.w, a1.w), a2.w);
            s1Q[i] = r;
            s1E[i] = __hadd2(__hadd2(lE[i], lE[i + 1]), lE[i + 2]);
        }
        __syncthreads();

        // ---- phase 2: 7-tap stride-3 stage ----
        HQ s = s1Q[z];
        __half2 e = s1E[z];
#pragma unroll
        for (int j = 3; j <= 18; j += 3) {
            HQ v = s1Q[z + j];
            s.x = __hadd2(s.x, v.x);
            s.y = __hadd2(s.y, v.y);
            s.z = __hadd2(s.z, v.z);
            s.w = __hadd2(s.w, v.w);
            e = __hadd2(e, s1E[z + j]);
        }

        // ---- ring write ----
        g_rq[ro] = s;
        g_re[ro] = e;

        // ---- y running sums in native half ----
        // line0 (y): add lane0 of new pair, sub lane1 of pair it-11
        c0 = __hadd(c0, __hsub(__low2half(s.x), __high2half(hd.x)));
        c1 = __hadd(c1, __hsub(__low2half(s.y), __high2half(hd.y)));
        c2 = __hadd(c2, __hsub(__low2half(s.z), __high2half(hd.z)));
        c3 = __hadd(c3, __hsub(__low2half(s.w), __high2half(hd.w)));
        c4 = __hadd(c4, __hsub(__low2half(e),   __high2half(hed)));
        const __half a0 = c0, a1 = c1, a2 = c2, a3 = c3, a4 = c4;
        // line1 (y+1): add lane1 of new pair, sub lane0 of pair it-10
        c0 = __hadd(c0, __hsub(__high2half(s.x), __low2half(hn.x)));
        c1 = __hadd(c1, __hsub(__high2half(s.y), __low2half(hn.y)));
        c2 = __hadd(c2, __hsub(__high2half(s.z), __low2half(hn.z)));
        c3 = __hadd(c3, __hsub(__high2half(s.w), __low2half(hn.w)));
        c4 = __hadd(c4, __hsub(__high2half(e),   __low2half(hen)));

        const int yo = y - HALF;
        if (yo >= y0) {
            size_t qidx = (((size_t)(b * SX + x)) * YP + (yo >> 1)) * SZ + z;
            HQ w;
            w.x = __halves2half2(a0, c0);
            w.y = __halves2half2(a1, c1);
            w.z = __halves2half2(a2, c2);
            w.w = __halves2half2(a3, c3);
            g_q2[qidx] = w;
            g_e2[qidx] = __halves2half2(a4, c4);
        }
    }
}

// ---------------------------------------------------------------------------
// Pass C: x box filter over y-pair-packed data (two y-lines per load).
// Window sums in native half2; converts to fp32 only for cc. Fast divide.
// XSEG=8 -> 1536 blocks (10.4/SM). Unroll-4, batched loads (MLP 8).
// Deterministic partials; last block does a fixed-order final reduction.
// ---------------------------------------------------------------------------
__global__ __launch_bounds__(SZ, 6) void passC(float* __restrict__ out) {
    int bid = blockIdx.x;
    const int seg = bid % XSEG;
    int t = bid / XSEG;
    const int yp = t % YP;
    const int b = t / YP;
    const int z = threadIdx.x;

    const int x0 = seg * XLEN;
    const size_t strideX = (size_t)YP * SZ;
    const size_t base = ((size_t)b * SX) * strideX + (size_t)yp * SZ + z;

    const __half2 zero2 = __floats2half2_rn(0.f, 0.f);
    __half2 sI = zero2, sJ = zero2, sI2 = zero2, sJ2 = zero2, sIJ = zero2;

#pragma unroll
    for (int k = 0; k < WIN; k++) {
        const int xx = x0 - HALF + k;
        if (xx >= 0 && xx < SX) {
            size_t o = base + (size_t)xx * strideX;
            HQ h = g_q2[o];
            __half2 e = g_e2[o];
            sI  = __hadd2(sI,  h.x);
            sJ  = __hadd2(sJ,  h.y);
            sI2 = __hadd2(sI2, h.z);
            sJ2 = __hadd2(sJ2, h.w);
            sIJ = __hadd2(sIJ, e);
        }
    }

    const float inv_n = 1.0f / (float)(WIN * WIN * WIN);
    float acc = 0.f;

    for (int xb = 0; xb < XLEN; xb += 4) {
        HQ ha[4], hr[4];
        __half2 ea[4], er[4];
#pragma unroll
        for (int j = 0; j < 4; j++) {
            const int xa = x0 + xb + j + HALF + 1;
            ha[j].x = zero2; ha[j].y = zero2; ha[j].z = zero2; ha[j].w = zero2;
            ea[j] = zero2;
            if (xa < SX) {
                size_t o = base + (size_t)xa * strideX;
                ha[j] = g_q2[o]; ea[j] = g_e2[o];
            }
        }
#pragma unroll
        for (int j = 0; j < 4; j++) {
            const int xr = x0 + xb + j - HALF;
            hr[j].x = zero2; hr[j].y = zero2; hr[j].z = zero2; hr[j].w = zero2;
            er[j] = zero2;
            if (xr >= 0) {
                size_t o = base + (size_t)xr * strideX;
                hr[j] = g_q2[o]; er[j] = g_e2[o];
            }
        }
#pragma unroll
        for (int j = 0; j < 4; j++) {
            float2 fI  = __half22float2(sI);
            float2 fJ  = __half22float2(sJ);
            float2 fI2 = __half22float2(sI2);
            float2 fJ2 = __half22float2(sJ2);
            float2 fIJ = __half22float2(sIJ);
#pragma unroll
            for (int ln = 0; ln < 2; ln++) {
                float t0 = ln ? fI.y : fI.x;
                float t1 = ln ? fJ.y : fJ.x;
                float t2 = ln ? fI2.y : fI2.x;
                float t3 = ln ? fJ2.y : fJ2.x;
                float t4 = ln ? fIJ.y : fIJ.x;
                float cross = t4 - t0 * t1 * inv_n;
                float Ivar  = t2 - t0 * t0 * inv_n;
                float Jvar  = t3 - t1 * t1 * inv_n;
                acc += __fdividef(cross * cross, Ivar * Jvar + 1e-5f);
            }
            sI  = __hadd2(sI,  __hsub2(ha[j].x, hr[j].x));
            sJ  = __hadd2(sJ,  __hsub2(ha[j].y, hr[j].y));
            sI2 = __hadd2(sI2, __hsub2(ha[j].z, hr[j].z));
            sJ2 = __hadd2(sJ2, __hsub2(ha[j].w, hr[j].w));
            sIJ = __hadd2(sIJ, __hsub2(ea[j],   er[j]));
        }
    }

    // deterministic block reduction (160 threads = 5 warps)
    __shared__ float wsum[SZ / 32];
    __shared__ int isLast;
    float v = acc;
#pragma unroll
    for (int off = 16; off; off >>= 1)
        v += __shfl_down_sync(0xffffffffu, v, off);
    if ((threadIdx.x & 31) == 0) wsum[threadIdx.x >> 5] = v;
    __syncthreads();
    if (threadIdx.x == 0) {
        double tot = 0.0;
#pragma unroll
        for (int w = 0; w < SZ / 32; w++) tot += (double)wsum[w];
        g_part[bid] = tot;
        __threadfence();
        int n = atomicAdd(&g_count, 1);
        isLast = (n == NPART - 1);
    }
    __syncthreads();

    if (isLast) {
        __shared__ double sh[256];
        double cv = 0.0;
        const int chunk = 10;                // 160 * 10 = 1600 >= 1536
        int lo = threadIdx.x * chunk;
        for (int i = lo; i < lo + chunk && i < NPART; ++i)
            cv += g_part[i];
        sh[threadIdx.x] = cv;
        if (threadIdx.x < 256 - SZ) sh[SZ + threadIdx.x] = 0.0;
        __syncthreads();
        for (int s = 128; s; s >>= 1) {
            if (threadIdx.x < s) sh[threadIdx.x] += sh[threadIdx.x + s];
            __syncthreads();
        }
        if (threadIdx.x == 0) {
            out[0] = (float)(1.0 - sh[0] / (double)NF);
            g_count = 0;                      // reset for next graph replay
        }
    }
}

extern "C" void kernel_launch(void* const* d_in, const int* in_sizes, int n_in,
                              void* d_out, int out_size) {
    const float* I = (const float*)d_in[0];
    const float* J = (const float*)d_in[1];
    float* out = (float*)d_out;

    passAB<<<NBLK_AB, SZ>>>(I, J);
    passC<<<NPART, SZ>>>(out);
}

// round 11
// speedup vs baseline: 1.0339x; 1.0339x over previous
#include <cuda_runtime.h>
#include <cuda_fp16.h>

#define SB 2
#define SX 160
#define SY 192
#define SZ 160
#define WIN 21
#define HALF 10
#define NF 9830400ull          // SB*SX*SY*SZ
#define YP (SY / 2)            // 96 y-pairs
#define YSEG 2
#define YL (SY / YSEG)         // 96
#define XSEG 4
#define XLEN (SX / XSEG)       // 40
#define NPART (SB * YP * XSEG) // 768
#define LPAD (SZ + 2 * HALF)   // 180
#define S1N (SZ + 18)          // stage1 physical range
#define RDEP 12                // ring depth in y-PAIRS
#define NBLK_AB (SB * SX * YSEG)

// 4 channels packed as half2 (lane = y parity): x=(I), y=(J), z=(I2), w=(J2)
struct __align__(16) HQ { __half2 x, y, z, w; };

__device__ HQ g_q2[NF / 2];            // y-pair-packed output of passAB
__device__ __half2 g_e2[NF / 2];       // IJ channel
__device__ HQ g_rq[(size_t)NBLK_AB * RDEP * SZ];      // gmem ring (L2-resident)
__device__ __half2 g_re[(size_t)NBLK_AB * RDEP * SZ];
__device__ double g_part[NPART];
__device__ int g_count;

// ---------------------------------------------------------------------------
// Fused pass A+B: 2 y-pairs (4 lines) per barrier set. z-filter = 3-tap then
// 7-tap-stride-3 packed HADD2 stages, run for both pairs between the same
// barriers (doubled inter-barrier ILP, halved barrier count). y-filter =
// per-thread running sums in native half; subtrahends from a GMEM pair-ring
// (3 entries prefetched at iteration top, consumed after phase 2).
// ---------------------------------------------------------------------------
__global__ __launch_bounds__(SZ) void passAB(const float* __restrict__ I,
                                             const float* __restrict__ J) {
    __shared__ HQ      lQ[2][LPAD];
    __shared__ __half2 lE[2][LPAD];
    __shared__ HQ      s1Q[2][S1N];
    __shared__ __half2 s1E[2][S1N];

    const int z = threadIdx.x;
    int bid = blockIdx.x;
    const int seg = bid % YSEG;
    int t = bid / YSEG;
    const int x = t % SX;
    const int b = t / SX;

    const __half2 zero2 = __floats2half2_rn(0.f, 0.f);
    const __half zeroh = __float2half(0.f);

    if (z < HALF) {
        HQ z4; z4.x = zero2; z4.y = zero2; z4.z = zero2; z4.w = zero2;
#pragma unroll
        for (int p = 0; p < 2; p++) {
            lQ[p][z] = z4; lQ[p][SZ + HALF + z] = z4;
            lE[p][z] = zero2; lE[p][SZ + HALF + z] = zero2;
        }
    }

    const int y0 = seg * YL;
    const int y1 = y0 + YL;
    const int ystart = (y0 - HALF > 0) ? (y0 - HALF) : 0;  // even
    const size_t planeBase = ((size_t)(b * SX + x)) * SY * SZ;
    const size_t ringBase = (size_t)bid * RDEP;

    __half c0 = zeroh, c1 = zeroh, c2 = zeroh, c3 = zeroh, c4 = zeroh;

    // preload the first 4 input lines
    float pi[4], pj[4];
#pragma unroll
    for (int l = 0; l < 4; l++) {
        pi[l] = 0.f; pj[l] = 0.f;
        const int yy = ystart + l;
        if (yy < SY) {
            size_t o = planeBase + (size_t)yy * SZ + z;
            pi[l] = I[o]; pj[l] = J[o];
        }
    }

    __syncthreads();

    for (int y = ystart; y < y1 + HALF; y += 4) {
        const int ip = (y - ystart) >> 1;  // global pair index of pair A

        // ---- ring prefetch: pairs ip-11, ip-10, ip-9 (consume after ph2) ----
        HQ hA, hM, hB; __half2 eA_, eM_, eB_;
        hA.x = zero2; hA.y = zero2; hA.z = zero2; hA.w = zero2; eA_ = zero2;
        hM = hA; eM_ = zero2; hB = hA; eB_ = zero2;
        if (ip >= 11) {
            size_t r = (ringBase + (ip - 11) % RDEP) * SZ + z;
            hA = g_rq[r]; eA_ = g_re[r];
        }
        if (ip >= 10) {
            size_t r = (ringBase + (ip - 10) % RDEP) * SZ + z;
            hM = g_rq[r]; eM_ = g_re[r];
        }
        if (ip >= 9) {
            size_t r = (ringBase + (ip - 9) % RDEP) * SZ + z;
            hB = g_rq[r]; eB_ = g_re[r];
        }

        // ---- phase 0: stage both pairs' products ----
#pragma unroll
        for (int p = 0; p < 2; p++) {
            HQ h;
            h.x = __floats2half2_rn(pi[2 * p], pi[2 * p + 1]);
            h.y = __floats2half2_rn(pj[2 * p], pj[2 * p + 1]);
            h.z = __hmul2(h.x, h.x);
            h.w = __hmul2(h.y, h.y);
            lQ[p][HALF + z] = h;
            lE[p][HALF + z] = __hmul2(h.x, h.y);
        }

        // ---- prefetch next 4 lines ----
#pragma unroll
        for (int l = 0; l < 4; l++) {
            pi[l] = 0.f; pj[l] = 0.f;
            const int yn = y + 4 + l;
            if (yn < SY) {
                size_t o = planeBase + (size_t)yn * SZ + z;
                pi[l] = I[o]; pj[l] = J[o];
            }
        }
        __syncthreads();

        // ---- phase 1: 3-tap stage for both pairs ----
#pragma unroll
        for (int p = 0; p < 2; p++) {
            {
                const int i = z;
                HQ a0 = lQ[p][i], a1 = lQ[p][i + 1], a2 = lQ[p][i + 2];
                HQ r;
                r.x = __hadd2(__hadd2(a0.x, a1.x), a2.x);
                r.y = __hadd2(__hadd2(a0.y, a1.y), a2.y);
                r.z = __hadd2(__hadd2(a0.z, a1.z), a2.z);
                r.w = __hadd2(__hadd2(a0.w, a1.w), a2.w);
                s1Q[p][i] = r;
                s1E[p][i] = __hadd2(__hadd2(lE[p][i], lE[p][i + 1]), lE[p][i + 2]);
            }
            if (z < S1N - SZ) {
                const int i = SZ + z;
                HQ a0 = lQ[p][i], a1 = lQ[p][i + 1], a2 = lQ[p][i + 2];
                HQ r;
                r.x = __hadd2(__hadd2(a0.x, a1.x), a2.x);
                r.y = __hadd2(__hadd2(a0.y, a1.y), a2.y);
                r.z = __hadd2(__hadd2(a0.z, a1.z), a2.z);
                r.w = __hadd2(__hadd2(a0.w, a1.w), a2.w);
                s1Q[p][i] = r;
                s1E[p][i] = __hadd2(__hadd2(lE[p][i], lE[p][i + 1]), lE[p][i + 2]);
            }
        }
        __syncthreads();

        // ---- phase 2: 7-tap stride-3 stage, both pairs interleaved ----
        HQ sA = s1Q[0][z], sB = s1Q[1][z];
        __half2 eA = s1E[0][z], eB = s1E[1][z];
#pragma unroll
        for (int j = 3; j <= 18; j += 3) {
            HQ vA = s1Q[0][z + j], vB = s1Q[1][z + j];
            sA.x = __hadd2(sA.x, vA.x); sB.x = __hadd2(sB.x, vB.x);
            sA.y = __hadd2(sA.y, vA.y); sB.y = __hadd2(sB.y, vB.y);
            sA.z = __hadd2(sA.z, vA.z); sB.z = __hadd2(sB.z, vB.z);
            sA.w = __hadd2(sA.w, vA.w); sB.w = __hadd2(sB.w, vB.w);
            eA = __hadd2(eA, s1E[0][z + j]); eB = __hadd2(eB, s1E[1][z + j]);
        }

        // ---- ring writes (reads already prefetched) ----
        {
            size_t rA = (ringBase + ip % RDEP) * SZ + z;
            size_t rB = (ringBase + (ip + 1) % RDEP) * SZ + z;
            g_rq[rA] = sA; g_re[rA] = eA;
            g_rq[rB] = sB; g_re[rB] = eB;
        }

        // ---- y running sums (native half), 4 lines in order ----
        // line y:   add lo(sA), sub hi(pair ip-11)
        c0 = __hadd(c0, __hsub(__low2half(sA.x), __high2half(hA.x)));
        c1 = __hadd(c1, __hsub(__low2half(sA.y), __high2half(hA.y)));
        c2 = __hadd(c2, __hsub(__low2half(sA.z), __high2half(hA.z)));
        c3 = __hadd(c3, __hsub(__low2half(sA.w), __high2half(hA.w)));
        c4 = __hadd(c4, __hsub(__low2half(eA),   __high2half(eA_)));
        const __half s00 = c0, s01 = c1, s02 = c2, s03 = c3, s04 = c4;
        // line y+1: add hi(sA), sub lo(pair ip-10)
        c0 = __hadd(c0, __hsub(__high2half(sA.x), __low2half(hM.x)));
        c1 = __hadd(c1, __hsub(__high2half(sA.y), __low2half(hM.y)));
        c2 = __hadd(c2, __hsub(__high2half(sA.z), __low2half(hM.z)));
        c3 = __hadd(c3, __hsub(__high2half(sA.w), __low2half(hM.w)));
        c4 = __hadd(c4, __hsub(__high2half(eA),   __low2half(eM_)));
        const __half s10 = c0, s11 = c1, s12 = c2, s13 = c3, s14 = c4;
        // line y+2: add lo(sB), sub hi(pair ip-10)
        c0 = __hadd(c0, __hsub(__low2half(sB.x), __high2half(hM.x)));
        c1 = __hadd(c1, __hsub(__low2half(sB.y), __high2half(hM.y)));
        c2 = __hadd(c2, __hsub(__low2half(sB.z), __high2half(hM.z)));
        c3 = __hadd(c3, __hsub(__low2half(sB.w), __high2half(hM.w)));
        c4 = __hadd(c4, __hsub(__low2half(eB),   __high2half(eM_)));
        const __half s20 = c0, s21 = c1, s22 = c2, s23 = c3, s24 = c4;
        // line y+3: add hi(sB), sub lo(pair ip-9)
        c0 = __hadd(c0, __hsub(__high2half(sB.x), __low2half(hB.x)));
        c1 = __hadd(c1, __hsub(__high2half(sB.y), __low2half(hB.y)));
        c2 = __hadd(c2, __hsub(__high2half(sB.z), __low2half(hB.z)));
        c3 = __hadd(c3, __hsub(__high2half(sB.w), __low2half(hB.w)));
        c4 = __hadd(c4, __hsub(__high2half(eB),   __low2half(eB_)));

        // ---- outputs: pairs (y-10, y-9) and (y-8, y-7) ----
        {
            const int yo = y - HALF;
            if (yo >= y0 && yo < y1) {
                size_t qidx = (((size_t)(b * SX + x)) * YP + (yo >> 1)) * SZ + z;
                HQ w;
                w.x = __halves2half2(s00, s10);
                w.y = __halves2half2(s01, s11);
                w.z = __halves2half2(s02, s12);
                w.w = __halves2half2(s03, s13);
                g_q2[qidx] = w;
                g_e2[qidx] = __halves2half2(s04, s14);
            }
        }
        {
            const int yo = y - HALF + 2;
            if (yo >= y0 && yo < y1) {
                size_t qidx = (((size_t)(b * SX + x)) * YP + (yo >> 1)) * SZ + z;
                HQ w;
                w.x = __halves2half2(s20, c0);
                w.y = __halves2half2(s21, c1);
                w.z = __halves2half2(s22, c2);
                w.w = __halves2half2(s23, c3);
                g_q2[qidx] = w;
                g_e2[qidx] = __halves2half2(s24, c4);
            }
        }
    }
}

// ---------------------------------------------------------------------------
// Pass C: x box filter over y-pair-packed data (two y-lines per load).
// Window sums in native half2; converts to fp32 only for cc. Fast divide.
// Unroll-4 with batched loads (MLP 8). Deterministic partials; last block
// does a fixed-order final reduction.
// ---------------------------------------------------------------------------
__global__ __launch_bounds__(SZ, 6) void passC(float* __restrict__ out) {
    int bid = blockIdx.x;
    const int seg = bid % XSEG;
    int t = bid / XSEG;
    const int yp = t % YP;
    const int b = t / YP;
    const int z = threadIdx.x;

    const int x0 = seg * XLEN;
    const size_t strideX = (size_t)YP * SZ;
    const size_t base = ((size_t)b * SX) * strideX + (size_t)yp * SZ + z;

    const __half2 zero2 = __floats2half2_rn(0.f, 0.f);
    __half2 sI = zero2, sJ = zero2, sI2 = zero2, sJ2 = zero2, sIJ = zero2;

#pragma unroll
    for (int k = 0; k < WIN; k++) {
        const int xx = x0 - HALF + k;
        if (xx >= 0 && xx < SX) {
            size_t o = base + (size_t)xx * strideX;
            HQ h = g_q2[o];
            __half2 e = g_e2[o];
            sI  = __hadd2(sI,  h.x);
            sJ  = __hadd2(sJ,  h.y);
            sI2 = __hadd2(sI2, h.z);
            sJ2 = __hadd2(sJ2, h.w);
            sIJ = __hadd2(sIJ, e);
        }
    }

    const float inv_n = 1.0f / (float)(WIN * WIN * WIN);
    float acc = 0.f;

    for (int xb = 0; xb < XLEN; xb += 4) {
        HQ ha[4], hr[4];
        __half2 ea[4], er[4];
#pragma unroll
        for (int j = 0; j < 4; j++) {
            const int xa = x0 + xb + j + HALF + 1;
            ha[j].x = zero2; ha[j].y = zero2; ha[j].z = zero2; ha[j].w = zero2;
            ea[j] = zero2;
            if (xa < SX) {
                size_t o = base + (size_t)xa * strideX;
                ha[j] = g_q2[o]; ea[j] = g_e2[o];
            }
        }
#pragma unroll
        for (int j = 0; j < 4; j++) {
            const int xr = x0 + xb + j - HALF;
            hr[j].x = zero2; hr[j].y = zero2; hr[j].z = zero2; hr[j].w = zero2;
            er[j] = zero2;
            if (xr >= 0) {
                size_t o = base + (size_t)xr * strideX;
                hr[j] = g_q2[o]; er[j] = g_e2[o];
            }
        }
#pragma unroll
        for (int j = 0; j < 4; j++) {
            float2 fI  = __half22float2(sI);
            float2 fJ  = __half22float2(sJ);
            float2 fI2 = __half22float2(sI2);
            float2 fJ2 = __half22float2(sJ2);
            float2 fIJ = __half22float2(sIJ);
#pragma unroll
            for (int ln = 0; ln < 2; ln++) {
                float t0 = ln ? fI.y : fI.x;
                float t1 = ln ? fJ.y : fJ.x;
                float t2 = ln ? fI2.y : fI2.x;
                float t3 = ln ? fJ2.y : fJ2.x;
                float t4 = ln ? fIJ.y : fIJ.x;
                float cross = t4 - t0 * t1 * inv_n;
                float Ivar  = t2 - t0 * t0 * inv_n;
                float Jvar  = t3 - t1 * t1 * inv_n;
                acc += __fdividef(cross * cross, Ivar * Jvar + 1e-5f);
            }
            sI  = __hadd2(sI,  __hsub2(ha[j].x, hr[j].x));
            sJ  = __hadd2(sJ,  __hsub2(ha[j].y, hr[j].y));
            sI2 = __hadd2(sI2, __hsub2(ha[j].z, hr[j].z));
            sJ2 = __hadd2(sJ2, __hsub2(ha[j].w, hr[j].w));
            sIJ = __hadd2(sIJ, __hsub2(ea[j],   er[j]));
        }
    }

    // deterministic block reduction (160 threads = 5 warps)
    __shared__ float wsum[SZ / 32];
    __shared__ int isLast;
    float v = acc;
#pragma unroll
    for (int off = 16; off; off >>= 1)
        v += __shfl_down_sync(0xffffffffu, v, off);
    if ((threadIdx.x & 31) == 0) wsum[threadIdx.x >> 5] = v;
    __syncthreads();
    if (threadIdx.x == 0) {
        double tot = 0.0;
#pragma unroll
        for (int w = 0; w < SZ / 32; w++) tot += (double)wsum[w];
        g_part[bid] = tot;
        __threadfence();
        int n = atomicAdd(&g_count, 1);
        isLast = (n == NPART - 1);
    }
    __syncthreads();

    if (isLast) {
        __shared__ double sh[256];
        double cv = 0.0;
        const int chunk = 5;                 // 160 * 5 = 800 >= 768
        int lo = threadIdx.x * chunk;
        for (int i = lo; i < lo + chunk && i < NPART; ++i)
            cv += g_part[i];
        sh[threadIdx.x] = cv;
        if (threadIdx.x < 256 - SZ) sh[SZ + threadIdx.x] = 0.0;
        __syncthreads();
        for (int s = 128; s; s >>= 1) {
            if (threadIdx.x < s) sh[threadIdx.x] += sh[threadIdx.x + s];
            __syncthreads();
        }
        if (threadIdx.x == 0) {
            out[0] = (float)(1.0 - sh[0] / (double)NF);
            g_count = 0;                      // reset for next graph replay
        }
    }
}

extern "C" void kernel_launch(void* const* d_in, const int* in_sizes, int n_in,
                              void* d_out, int out_size) {
    const float* I = (const float*)d_in[0];
    const float* J = (const float*)d_in[1];
    float* out = (float*)d_out;

    passAB<<<NBLK_AB, SZ>>>(I, J);
    passC<<<NPART, SZ>>>(out);
}

// round 12
// speedup vs baseline: 1.0502x; 1.0158x over previous
#include <cuda_runtime.h>
#include <cuda_fp16.h>

#define SB 2
#define SX 160
#define SY 192
#define SZ 160
#define WIN 21
#define HALF 10
#define NF 9830400ull          // SB*SX*SY*SZ
#define YP (SY / 2)            // 96 y-pairs
#define YSEG 3
#define YL (SY / YSEG)         // 64
#define XSEG 4
#define XLEN (SX / XSEG)       // 40
#define NPART (SB * YP * XSEG) // 768
#define LPAD (SZ + 2 * HALF)   // 180
#define S1N (SZ + 18)          // stage1 physical range
#define RDEP 12                // ring depth in y-PAIRS
#define NBLK_AB (SB * SX * YSEG)

// 4 channels packed as half2 (lane = y parity): x=(I), y=(J), z=(I2), w=(J2)
struct __align__(16) HQ { __half2 x, y, z, w; };

__device__ HQ g_q2[NF / 2];            // y-pair-packed output of passAB
__device__ __half2 g_e2[NF / 2];       // IJ channel
__device__ HQ g_rq[(size_t)NBLK_AB * RDEP * SZ];      // gmem ring (L2-resident)
__device__ __half2 g_re[(size_t)NBLK_AB * RDEP * SZ];
__device__ double g_part[NPART];
__device__ int g_count;

// ---------------------------------------------------------------------------
// Fused pass A+B: 2 y-pairs (4 lines) per barrier set. z-filter = 3-tap then
// 7-tap-stride-3 packed HADD2 stages. y-filter = per-thread running sums in
// native half; subtrahends from a GMEM pair-ring (3 entries prefetched at
// iteration top, consumed after phase 2). launch_bounds(160,6) caps regs so
// 6 CTAs/SM actually fit; YSEG=3 provides the grid (960 blocks, 6.5/SM).
// ---------------------------------------------------------------------------
__global__ __launch_bounds__(SZ, 6) void passAB(const float* __restrict__ I,
                                                const float* __restrict__ J) {
    __shared__ HQ      lQ[2][LPAD];
    __shared__ __half2 lE[2][LPAD];
    __shared__ HQ      s1Q[2][S1N];
    __shared__ __half2 s1E[2][S1N];

    const int z = threadIdx.x;
    int bid = blockIdx.x;
    const int seg = bid % YSEG;
    int t = bid / YSEG;
    const int x = t % SX;
    const int b = t / SX;

    const __half2 zero2 = __floats2half2_rn(0.f, 0.f);
    const __half zeroh = __float2half(0.f);

    if (z < HALF) {
        HQ z4; z4.x = zero2; z4.y = zero2; z4.z = zero2; z4.w = zero2;
#pragma unroll
        for (int p = 0; p < 2; p++) {
            lQ[p][z] = z4; lQ[p][SZ + HALF + z] = z4;
            lE[p][z] = zero2; lE[p][SZ + HALF + z] = zero2;
        }
    }

    const int y0 = seg * YL;
    const int y1 = y0 + YL;
    const int ystart = (y0 - HALF > 0) ? (y0 - HALF) : 0;  // even (0,54,118)
    const size_t planeBase = ((size_t)(b * SX + x)) * SY * SZ;
    const size_t ringBase = (size_t)bid * RDEP;

    __half c0 = zeroh, c1 = zeroh, c2 = zeroh, c3 = zeroh, c4 = zeroh;

    // preload the first 4 input lines
    float pi[4], pj[4];
#pragma unroll
    for (int l = 0; l < 4; l++) {
        pi[l] = 0.f; pj[l] = 0.f;
        const int yy = ystart + l;
        if (yy < SY) {
            size_t o = planeBase + (size_t)yy * SZ + z;
            pi[l] = I[o]; pj[l] = J[o];
        }
    }

    __syncthreads();

    for (int y = ystart; y < y1 + HALF; y += 4) {
        const int ip = (y - ystart) >> 1;  // pair index of pair A

        // ---- ring prefetch: pairs ip-11, ip-10, ip-9 (consume after ph2) ----
        HQ hA, hM, hB; __half2 eA_, eM_, eB_;
        hA.x = zero2; hA.y = zero2; hA.z = zero2; hA.w = zero2; eA_ = zero2;
        hM = hA; eM_ = zero2; hB = hA; eB_ = zero2;
        if (ip >= 11) {
            size_t r = (ringBase + (ip - 11) % RDEP) * SZ + z;
            hA = g_rq[r]; eA_ = g_re[r];
        }
        if (ip >= 10) {
            size_t r = (ringBase + (ip - 10) % RDEP) * SZ + z;
            hM = g_rq[r]; eM_ = g_re[r];
        }
        if (ip >= 9) {
            size_t r = (ringBase + (ip - 9) % RDEP) * SZ + z;
            hB = g_rq[r]; eB_ = g_re[r];
        }

        // ---- phase 0: stage both pairs' products ----
#pragma unroll
        for (int p = 0; p < 2; p++) {
            HQ h;
            h.x = __floats2half2_rn(pi[2 * p], pi[2 * p + 1]);
            h.y = __floats2half2_rn(pj[2 * p], pj[2 * p + 1]);
            h.z = __hmul2(h.x, h.x);
            h.w = __hmul2(h.y, h.y);
            lQ[p][HALF + z] = h;
            lE[p][HALF + z] = __hmul2(h.x, h.y);
        }

        // ---- prefetch next 4 lines ----
#pragma unroll
        for (int l = 0; l < 4; l++) {
            pi[l] = 0.f; pj[l] = 0.f;
            const int yn = y + 4 + l;
            if (yn < SY) {
                size_t o = planeBase + (size_t)yn * SZ + z;
                pi[l] = I[o]; pj[l] = J[o];
            }
        }
        __syncthreads();

        // ---- phase 1: 3-tap stage for both pairs ----
#pragma unroll
        for (int p = 0; p < 2; p++) {
            {
                const int i = z;
                HQ a0 = lQ[p][i], a1 = lQ[p][i + 1], a2 = lQ[p][i + 2];
                HQ r;
                r.x = __hadd2(__hadd2(a0.x, a1.x), a2.x);
                r.y = __hadd2(__hadd2(a0.y, a1.y), a2.y);
                r.z = __hadd2(__hadd2(a0.z, a1.z), a2.z);
                r.w = __hadd2(__hadd2(a0.w, a1.w), a2.w);
                s1Q[p][i] = r;
                s1E[p][i] = __hadd2(__hadd2(lE[p][i], lE[p][i + 1]), lE[p][i + 2]);
            }
            if (z < S1N - SZ) {
                const int i = SZ + z;
                HQ a0 = lQ[p][i], a1 = lQ[p][i + 1], a2 = lQ[p][i + 2];
                HQ r;
                r.x = __hadd2(__hadd2(a0.x, a1.x), a2.x);
                r.y = __hadd2(__hadd2(a0.y, a1.y), a2.y);
                r.z = __hadd2(__hadd2(a0.z, a1.z), a2.z);
                r.w = __hadd2(__hadd2(a0.w, a1.w), a2.w);
                s1Q[p][i] = r;
                s1E[p][i] = __hadd2(__hadd2(lE[p][i], lE[p][i + 1]), lE[p][i + 2]);
            }
        }
        __syncthreads();

        // ---- phase 2: 7-tap stride-3 stage, both pairs interleaved ----
        HQ sA = s1Q[0][z], sB = s1Q[1][z];
        __half2 eA = s1E[0][z], eB = s1E[1][z];
#pragma unroll
        for (int j = 3; j <= 18; j += 3) {
            HQ vA = s1Q[0][z + j], vB = s1Q[1][z + j];
            sA.x = __hadd2(sA.x, vA.x); sB.x = __hadd2(sB.x, vB.x);
            sA.y = __hadd2(sA.y, vA.y); sB.y = __hadd2(sB.y, vB.y);
            sA.z = __hadd2(sA.z, vA.z); sB.z = __hadd2(sB.z, vB.z);
            sA.w = __hadd2(sA.w, vA.w); sB.w = __hadd2(sB.w, vB.w);
            eA = __hadd2(eA, s1E[0][z + j]); eB = __hadd2(eB, s1E[1][z + j]);
        }

        // ---- ring writes (reads already prefetched) ----
        {
            size_t rA = (ringBase + ip % RDEP) * SZ + z;
            size_t rB = (ringBase + (ip + 1) % RDEP) * SZ + z;
            g_rq[rA] = sA; g_re[rA] = eA;
            g_rq[rB] = sB; g_re[rB] = eB;
        }

        // ---- y running sums (native half), 4 lines in order ----
        c0 = __hadd(c0, __hsub(__low2half(sA.x), __high2half(hA.x)));
        c1 = __hadd(c1, __hsub(__low2half(sA.y), __high2half(hA.y)));
        c2 = __hadd(c2, __hsub(__low2half(sA.z), __high2half(hA.z)));
        c3 = __hadd(c3, __hsub(__low2half(sA.w), __high2half(hA.w)));
        c4 = __hadd(c4, __hsub(__low2half(eA),   __high2half(eA_)));
        const __half s00 = c0, s01 = c1, s02 = c2, s03 = c3, s04 = c4;
        c0 = __hadd(c0, __hsub(__high2half(sA.x), __low2half(hM.x)));
        c1 = __hadd(c1, __hsub(__high2half(sA.y), __low2half(hM.y)));
        c2 = __hadd(c2, __hsub(__high2half(sA.z), __low2half(hM.z)));
        c3 = __hadd(c3, __hsub(__high2half(sA.w), __low2half(hM.w)));
        c4 = __hadd(c4, __hsub(__high2half(eA),   __low2half(eM_)));
        const __half s10 = c0, s11 = c1, s12 = c2, s13 = c3, s14 = c4;
        c0 = __hadd(c0, __hsub(__low2half(sB.x), __high2half(hM.x)));
        c1 = __hadd(c1, __hsub(__low2half(sB.y), __high2half(hM.y)));
        c2 = __hadd(c2, __hsub(__low2half(sB.z), __high2half(hM.z)));
        c3 = __hadd(c3, __hsub(__low2half(sB.w), __high2half(hM.w)));
        c4 = __hadd(c4, __hsub(__low2half(eB),   __high2half(eM_)));
        const __half s20 = c0, s21 = c1, s22 = c2, s23 = c3, s24 = c4;
        c0 = __hadd(c0, __hsub(__high2half(sB.x), __low2half(hB.x)));
        c1 = __hadd(c1, __hsub(__high2half(sB.y), __low2half(hB.y)));
        c2 = __hadd(c2, __hsub(__high2half(sB.z), __low2half(hB.z)));
        c3 = __hadd(c3, __hsub(__high2half(sB.w), __low2half(hB.w)));
        c4 = __hadd(c4, __hsub(__high2half(eB),   __low2half(eB_)));

        // ---- outputs: pairs (y-10, y-9) and (y-8, y-7) ----
        {
            const int yo = y - HALF;
            if (yo >= y0 && yo < y1) {
                size_t qidx = (((size_t)(b * SX + x)) * YP + (yo >> 1)) * SZ + z;
                HQ w;
                w.x = __halves2half2(s00, s10);
                w.y = __halves2half2(s01, s11);
                w.z = __halves2half2(s02, s12);
                w.w = __halves2half2(s03, s13);
                g_q2[qidx] = w;
                g_e2[qidx] = __halves2half2(s04, s14);
            }
        }
        {
            const int yo = y - HALF + 2;
            if (yo >= y0 && yo < y1) {
                size_t qidx = (((size_t)(b * SX + x)) * YP + (yo >> 1)) * SZ + z;
                HQ w;
                w.x = __halves2half2(s20, c0);
                w.y = __halves2half2(s21, c1);
                w.z = __halves2half2(s22, c2);
                w.w = __halves2half2(s23, c3);
                g_q2[qidx] = w;
                g_e2[qidx] = __halves2half2(s24, c4);
            }
        }
    }
}

// ---------------------------------------------------------------------------
// Pass C: x box filter over y-pair-packed data (two y-lines per load).
// Window sums in native half2; converts to fp32 only for cc. Fast divide.
// Unroll-4 with batched loads (MLP 8). Deterministic partials; last block
// does a fixed-order final reduction.
// ---------------------------------------------------------------------------
__global__ __launch_bounds__(SZ, 6) void passC(float* __restrict__ out) {
    int bid = blockIdx.x;
    const int seg = bid % XSEG;
    int t = bid / XSEG;
    const int yp = t % YP;
    const int b = t / YP;
    const int z = threadIdx.x;

    const int x0 = seg * XLEN;
    const size_t strideX = (size_t)YP * SZ;
    const size_t base = ((size_t)b * SX) * strideX + (size_t)yp * SZ + z;

    const __half2 zero2 = __floats2half2_rn(0.f, 0.f);
    __half2 sI = zero2, sJ = zero2, sI2 = zero2, sJ2 = zero2, sIJ = zero2;

#pragma unroll
    for (int k = 0; k < WIN; k++) {
        const int xx = x0 - HALF + k;
        if (xx >= 0 && xx < SX) {
            size_t o = base + (size_t)xx * strideX;
            HQ h = g_q2[o];
            __half2 e = g_e2[o];
            sI  = __hadd2(sI,  h.x);
            sJ  = __hadd2(sJ,  h.y);
            sI2 = __hadd2(sI2, h.z);
            sJ2 = __hadd2(sJ2, h.w);
            sIJ = __hadd2(sIJ, e);
        }
    }

    const float inv_n = 1.0f / (float)(WIN * WIN * WIN);
    float acc = 0.f;

    for (int xb = 0; xb < XLEN; xb += 4) {
        HQ ha[4], hr[4];
        __half2 ea[4], er[4];
#pragma unroll
        for (int j = 0; j < 4; j++) {
            const int xa = x0 + xb + j + HALF + 1;
            ha[j].x = zero2; ha[j].y = zero2; ha[j].z = zero2; ha[j].w = zero2;
            ea[j] = zero2;
            if (xa < SX) {
                size_t o = base + (size_t)xa * strideX;
                ha[j] = g_q2[o]; ea[j] = g_e2[o];
            }
        }
#pragma unroll
        for (int j = 0; j < 4; j++) {
            const int xr = x0 + xb + j - HALF;
            hr[j].x = zero2; hr[j].y = zero2; hr[j].z = zero2; hr[j].w = zero2;
            er[j] = zero2;
            if (xr >= 0) {
                size_t o = base + (size_t)xr * strideX;
                hr[j] = g_q2[o]; er[j] = g_e2[o];
            }
        }
#pragma unroll
        for (int j = 0; j < 4; j++) {
            float2 fI  = __half22float2(sI);
            float2 fJ  = __half22float2(sJ);
            float2 fI2 = __half22float2(sI2);
            float2 fJ2 = __half22float2(sJ2);
            float2 fIJ = __half22float2(sIJ);
#pragma unroll
            for (int ln = 0; ln < 2; ln++) {
                float t0 = ln ? fI.y : fI.x;
                float t1 = ln ? fJ.y : fJ.x;
                float t2 = ln ? fI2.y : fI2.x;
                float t3 = ln ? fJ2.y : fJ2.x;
                float t4 = ln ? fIJ.y : fIJ.x;
                float cross = t4 - t0 * t1 * inv_n;
                float Ivar  = t2 - t0 * t0 * inv_n;
                float Jvar  = t3 - t1 * t1 * inv_n;
                acc += __fdividef(cross * cross, Ivar * Jvar + 1e-5f);
            }
            sI  = __hadd2(sI,  __hsub2(ha[j].x, hr[j].x));
            sJ  = __hadd2(sJ,  __hsub2(ha[j].y, hr[j].y));
            sI2 = __hadd2(sI2, __hsub2(ha[j].z, hr[j].z));
            sJ2 = __hadd2(sJ2, __hsub2(ha[j].w, hr[j].w));
            sIJ = __hadd2(sIJ, __hsub2(ea[j],   er[j]));
        }
    }

    // deterministic block reduction (160 threads = 5 warps)
    __shared__ float wsum[SZ / 32];
    __shared__ int isLast;
    float v = acc;
#pragma unroll
    for (int off = 16; off; off >>= 1)
        v += __shfl_down_sync(0xffffffffu, v, off);
    if ((threadIdx.x & 31) == 0) wsum[threadIdx.x >> 5] = v;
    __syncthreads();
    if (threadIdx.x == 0) {
        double tot = 0.0;
#pragma unroll
        for (int w = 0; w < SZ / 32; w++) tot += (double)wsum[w];
        g_part[bid] = tot;
        __threadfence();
        int n = atomicAdd(&g_count, 1);
        isLast = (n == NPART - 1);
    }
    __syncthreads();

    if (isLast) {
        __shared__ double sh[256];
        double cv = 0.0;
        const int chunk = 5;                 // 160 * 5 = 800 >= 768
        int lo = threadIdx.x * chunk;
        for (int i = lo; i < lo + chunk && i < NPART; ++i)
            cv += g_part[i];
        sh[threadIdx.x] = cv;
        if (threadIdx.x < 256 - SZ) sh[SZ + threadIdx.x] = 0.0;
        __syncthreads();
        for (int s = 128; s; s >>= 1) {
            if (threadIdx.x < s) sh[threadIdx.x] += sh[threadIdx.x + s];
            __syncthreads();
        }
        if (threadIdx.x == 0) {
            out[0] = (float)(1.0 - sh[0] / (double)NF);
            g_count = 0;                      // reset for next graph replay
        }
    }
}

extern "C" void kernel_launch(void* const* d_in, const int* in_sizes, int n_in,
                              void* d_out, int out_size) {
    const float* I = (const float*)d_in[0];
    const float* J = (const float*)d_in[1];
    float* out = (float*)d_out;

    passAB<<<NBLK_AB, SZ>>>(I, J);
    passC<<<NPART, SZ>>>(out);
}